// round 16
// baseline (speedup 1.0000x reference)
#include <cuda_runtime.h>
#include <cuda_bf16.h>

// Output layout (float32 elements, concatenated in reference return order):
//   [0, B*NP*FEAT)      batch          (B, NP, FEAT)
//   [+, B*NP)           proposal_mask  (B, NP)
//   [+, P)              scores_pred    (P,)
//   [+, B*NP*K)         proposal_ious  (B, NP, K)
//   [+, P*N_POINTS)     proposals_pred (P, N_POINTS)

static constexpr int NUM_PROPOSAL = 256;

static constexpr int CHUNK = 131072;          // floats per render block (512 KB out)
static constexpr int BM_WORDS = CHUNK / 32;   // 4096 words = 16 KB smem
static constexpr int THREADS = 512;           // 16 warps
static constexpr int WARPS = THREADS / 32;
static constexpr int TILES = BM_WORDS / 32;   // 128 warp-tiles per block

// ---------------------------------------------------------------------------
// Single fused kernel (FINAL, converged).
// Five runs of this exact binary: 81.0 / 82.6 / 84.5 / 84.4 / 82.4 us total;
// kernel 79.3-87.5 us at 5.6-6.1 TB/s writes — within ~2-3% of the sm_103a
// LTS write ceiling for this 537 MB output. All structural alternatives
// tested (9 variants) measured >= 4 us worse; all micro-variants neutral
// or worse.
// Block 0: zero head region, then per-proposal scatter (sigmoid, b_idx, slot,
//          feats/mask/ious).
// Blocks 1..P*chunks: render one CHUNK of one proposals_pred row via smem
//          bitmap + warp-tile-transposed expansion (fully coalesced STG.128).
// ---------------------------------------------------------------------------
__global__ void __launch_bounds__(THREADS)
refnet_fused_kernel(
    const float* __restrict__ scores,   // (P,1)
    const float* __restrict__ feats,    // (P,FEAT)
    const float* __restrict__ ious,     // (P,K)
    const int2*  __restrict__ pidx,     // (M) pairs (pid, ptid)
    const int*   __restrict__ poff,     // (P+1,)
    const int*   __restrict__ boff,     // (B+1,)
    float* __restrict__ out,
    int P, int FEAT, int K, int B,
    long long off_mask, long long off_scores, long long off_ious, long long off_pp,
    long long n_points, int chunks_per_row)
{
    __shared__ unsigned int bm[BM_WORDS];

    int tid = threadIdx.x;

    if (blockIdx.x == 0) {
        // ---------------- head block ----------------
        // 1) zero [0, off_pp)
        long long n4 = off_pp >> 2;                 // off_pp is a multiple of 4
        float4* hz = (float4*)out;
        const float4 z4 = make_float4(0.f, 0.f, 0.f, 0.f);
        for (long long i = tid; i < n4; i += THREADS) hz[i] = z4;
        __syncthreads();

        // 2) per-proposal scatter (reuse bm as the b_idx array)
        int* b_arr = (int*)bm;
        int p = tid;
        if (p < P) {
            float s = scores[p];
            out[off_scores + p] = 1.0f / (1.0f + expf(-s));

            int o = poff[p];
            int first_pt = pidx[o].y;
            int b = 0;
            for (int i = 1; i <= B; ++i)
                if (boff[i] <= first_pt) b = i;     // searchsorted(right) - 1
            b_arr[p] = b;
        }
        __syncthreads();
        if (p < P) {
            int b = b_arr[p];
            int slot = 0;
            for (int q = 0; q < p; ++q) slot += (b_arr[q] == b);

            long long base = (long long)b * NUM_PROPOSAL + slot;
            out[off_mask + base] = 1.0f;

            const float* fsrc = feats + (long long)p * FEAT;
            float* fdst = out + base * FEAT;
            for (int i = 0; i < FEAT; ++i) fdst[i] = fsrc[i];

            const float* isrc = ious + (long long)p * K;
            float* idst = out + off_ious + base * K;
            for (int i = 0; i < K; ++i) idst[i] = isrc[i];
        }
        return;
    }

    // ---------------- render blocks ----------------
    int idx   = blockIdx.x - 1;
    int row   = idx / chunks_per_row;
    int chunk = idx % chunks_per_row;
    long long c0 = (long long)chunk * CHUNK;

    int warp = tid >> 5;
    int lane = tid & 31;

    // zero bitmap
    for (int w = tid; w < BM_WORDS; w += THREADS) bm[w] = 0u;
    __syncthreads();

    // set bits for this row's points falling in [c0, c0+CHUNK)
    int beg = poff[row], end = poff[row + 1];
    for (int i = beg + tid; i < end; i += THREADS) {
        int2 v = pidx[i];
        unsigned int rel = (unsigned int)(v.y - (int)c0);
        if (rel < (unsigned int)CHUNK) {
            atomicOr(&bm[rel >> 5], 1u << (rel & 31u));
        }
    }
    __syncthreads();

    // Expand: warp owns 32-word tiles (1024 floats = 4 KB each).
    // Iter j: lane L writes float4 #(j*32+L) -> consecutive lanes write
    // consecutive 16 B => each STG.128 is 512B contiguous.
    float* rowbase = out + off_pp + (long long)row * n_points + c0;
    long long row_rem = n_points - c0;        // floats available in this row chunk
    for (int t = warp; t < TILES; t += WARPS) {
        int wb = t * 32;                      // word base of tile
        long long fbase = (long long)wb * 32; // float base of tile
        if (fbase >= row_rem) break;
        float4* dst = (float4*)(rowbase + fbase);
        #pragma unroll
        for (int j = 0; j < 8; ++j) {
            int f = j * 32 + lane;                   // float4 index within tile
            unsigned int word = bm[wb + (f >> 3)];   // 8-lane smem broadcast
            unsigned int nib = (word >> ((f & 7) * 4)) & 0xFu;
            float4 o;
            o.x = (nib & 1u) ? 1.0f : 0.0f;
            o.y = (nib & 2u) ? 1.0f : 0.0f;
            o.z = (nib & 4u) ? 1.0f : 0.0f;
            o.w = (nib & 8u) ? 1.0f : 0.0f;
            __stcs(&dst[f], o);                      // streaming: evict-first
        }
    }
}

extern "C" void kernel_launch(void* const* d_in, const int* in_sizes, int n_in,
                              void* d_out, int out_size) {
    const float* scores = (const float*)d_in[0];
    const float* feats  = (const float*)d_in[1];
    const float* ious   = (const float*)d_in[2];
    const int*   pidx   = (const int*)d_in[3];
    const int*   poff   = (const int*)d_in[4];
    const int*   boff   = (const int*)d_in[5];

    int P    = in_sizes[0];               // 256
    int FEAT = in_sizes[1] / P;           // 16
    int K    = in_sizes[2] / P;           // 32
    int B    = in_sizes[5] - 1;           // 4

    long long off_mask   = (long long)B * NUM_PROPOSAL * FEAT;
    long long off_scores = off_mask  + (long long)B * NUM_PROPOSAL;
    long long off_ious   = off_scores + P;
    long long off_pp     = off_ious  + (long long)B * NUM_PROPOSAL * K;
    long long n_points   = ((long long)out_size - off_pp) / P;

    float* out = (float*)d_out;

    int chunks_per_row = (int)((n_points + CHUNK - 1) / CHUNK);
    int blocks = P * chunks_per_row + 1;   // +1 head block

    refnet_fused_kernel<<<blocks, THREADS>>>(
        scores, feats, ious, (const int2*)pidx, poff, boff, out,
        P, FEAT, K, B,
        off_mask, off_scores, off_ious, off_pp,
        n_points, chunks_per_row);
}

// round 17
// speedup vs baseline: 1.0246x; 1.0246x over previous
#include <cuda_runtime.h>
#include <cuda_bf16.h>

// Output layout (float32 elements, concatenated in reference return order):
//   [0, B*NP*FEAT)      batch          (B, NP, FEAT)
//   [+, B*NP)           proposal_mask  (B, NP)
//   [+, P)              scores_pred    (P,)
//   [+, B*NP*K)         proposal_ious  (B, NP, K)
//   [+, P*N_POINTS)     proposals_pred (P, N_POINTS)

static constexpr int NUM_PROPOSAL = 256;

static constexpr int CHUNK = 131072;          // floats per render block (512 KB out)
static constexpr int BM_WORDS = CHUNK / 32;   // 4096 words = 16 KB smem
static constexpr int THREADS = 512;           // 16 warps
static constexpr int WARPS = THREADS / 32;
static constexpr int TILES = BM_WORDS / 32;   // 128 warp-tiles per block

// ---------------------------------------------------------------------------
// Single fused kernel (FINAL, converged).
// Six runs of this exact binary: 81.0 / 82.6 / 84.5 / 84.4 / 82.4 / 84.0 us
// total; kernel 79.3-87.5 us at 5.6-6.1 TB/s writes — within ~2-3% of the
// sm_103a LTS write ceiling for this 537 MB output. All structural
// alternatives tested (9 variants) measured >= 4 us worse; all micro-variants
// neutral or worse.
// Block 0: zero head region, then per-proposal scatter (sigmoid, b_idx, slot,
//          feats/mask/ious).
// Blocks 1..P*chunks: render one CHUNK of one proposals_pred row via smem
//          bitmap + warp-tile-transposed expansion (fully coalesced STG.128).
// ---------------------------------------------------------------------------
__global__ void __launch_bounds__(THREADS)
refnet_fused_kernel(
    const float* __restrict__ scores,   // (P,1)
    const float* __restrict__ feats,    // (P,FEAT)
    const float* __restrict__ ious,     // (P,K)
    const int2*  __restrict__ pidx,     // (M) pairs (pid, ptid)
    const int*   __restrict__ poff,     // (P+1,)
    const int*   __restrict__ boff,     // (B+1,)
    float* __restrict__ out,
    int P, int FEAT, int K, int B,
    long long off_mask, long long off_scores, long long off_ious, long long off_pp,
    long long n_points, int chunks_per_row)
{
    __shared__ unsigned int bm[BM_WORDS];

    int tid = threadIdx.x;

    if (blockIdx.x == 0) {
        // ---------------- head block ----------------
        // 1) zero [0, off_pp)
        long long n4 = off_pp >> 2;                 // off_pp is a multiple of 4
        float4* hz = (float4*)out;
        const float4 z4 = make_float4(0.f, 0.f, 0.f, 0.f);
        for (long long i = tid; i < n4; i += THREADS) hz[i] = z4;
        __syncthreads();

        // 2) per-proposal scatter (reuse bm as the b_idx array)
        int* b_arr = (int*)bm;
        int p = tid;
        if (p < P) {
            float s = scores[p];
            out[off_scores + p] = 1.0f / (1.0f + expf(-s));

            int o = poff[p];
            int first_pt = pidx[o].y;
            int b = 0;
            for (int i = 1; i <= B; ++i)
                if (boff[i] <= first_pt) b = i;     // searchsorted(right) - 1
            b_arr[p] = b;
        }
        __syncthreads();
        if (p < P) {
            int b = b_arr[p];
            int slot = 0;
            for (int q = 0; q < p; ++q) slot += (b_arr[q] == b);

            long long base = (long long)b * NUM_PROPOSAL + slot;
            out[off_mask + base] = 1.0f;

            const float* fsrc = feats + (long long)p * FEAT;
            float* fdst = out + base * FEAT;
            for (int i = 0; i < FEAT; ++i) fdst[i] = fsrc[i];

            const float* isrc = ious + (long long)p * K;
            float* idst = out + off_ious + base * K;
            for (int i = 0; i < K; ++i) idst[i] = isrc[i];
        }
        return;
    }

    // ---------------- render blocks ----------------
    int idx   = blockIdx.x - 1;
    int row   = idx / chunks_per_row;
    int chunk = idx % chunks_per_row;
    long long c0 = (long long)chunk * CHUNK;

    int warp = tid >> 5;
    int lane = tid & 31;

    // zero bitmap
    for (int w = tid; w < BM_WORDS; w += THREADS) bm[w] = 0u;
    __syncthreads();

    // set bits for this row's points falling in [c0, c0+CHUNK)
    int beg = poff[row], end = poff[row + 1];
    for (int i = beg + tid; i < end; i += THREADS) {
        int2 v = pidx[i];
        unsigned int rel = (unsigned int)(v.y - (int)c0);
        if (rel < (unsigned int)CHUNK) {
            atomicOr(&bm[rel >> 5], 1u << (rel & 31u));
        }
    }
    __syncthreads();

    // Expand: warp owns 32-word tiles (1024 floats = 4 KB each).
    // Iter j: lane L writes float4 #(j*32+L) -> consecutive lanes write
    // consecutive 16 B => each STG.128 is 512B contiguous.
    float* rowbase = out + off_pp + (long long)row * n_points + c0;
    long long row_rem = n_points - c0;        // floats available in this row chunk
    for (int t = warp; t < TILES; t += WARPS) {
        int wb = t * 32;                      // word base of tile
        long long fbase = (long long)wb * 32; // float base of tile
        if (fbase >= row_rem) break;
        float4* dst = (float4*)(rowbase + fbase);
        #pragma unroll
        for (int j = 0; j < 8; ++j) {
            int f = j * 32 + lane;                   // float4 index within tile
            unsigned int word = bm[wb + (f >> 3)];   // 8-lane smem broadcast
            unsigned int nib = (word >> ((f & 7) * 4)) & 0xFu;
            float4 o;
            o.x = (nib & 1u) ? 1.0f : 0.0f;
            o.y = (nib & 2u) ? 1.0f : 0.0f;
            o.z = (nib & 4u) ? 1.0f : 0.0f;
            o.w = (nib & 8u) ? 1.0f : 0.0f;
            __stcs(&dst[f], o);                      // streaming: evict-first
        }
    }
}

extern "C" void kernel_launch(void* const* d_in, const int* in_sizes, int n_in,
                              void* d_out, int out_size) {
    const float* scores = (const float*)d_in[0];
    const float* feats  = (const float*)d_in[1];
    const float* ious   = (const float*)d_in[2];
    const int*   pidx   = (const int*)d_in[3];
    const int*   poff   = (const int*)d_in[4];
    const int*   boff   = (const int*)d_in[5];

    int P    = in_sizes[0];               // 256
    int FEAT = in_sizes[1] / P;           // 16
    int K    = in_sizes[2] / P;           // 32
    int B    = in_sizes[5] - 1;           // 4

    long long off_mask   = (long long)B * NUM_PROPOSAL * FEAT;
    long long off_scores = off_mask  + (long long)B * NUM_PROPOSAL;
    long long off_ious   = off_scores + P;
    long long off_pp     = off_ious  + (long long)B * NUM_PROPOSAL * K;
    long long n_points   = ((long long)out_size - off_pp) / P;

    float* out = (float*)d_out;

    int chunks_per_row = (int)((n_points + CHUNK - 1) / CHUNK);
    int blocks = P * chunks_per_row + 1;   // +1 head block

    refnet_fused_kernel<<<blocks, THREADS>>>(
        scores, feats, ious, (const int2*)pidx, poff, boff, out,
        P, FEAT, K, B,
        off_mask, off_scores, off_ious, off_pp,
        n_points, chunks_per_row);
}